// round 4
// baseline (speedup 1.0000x reference)
#include <cuda_runtime.h>
#include <math.h>

#define F    1024
#define NJ   64
#define C    256
#define HID  1024
#define H    8
#define D    128

#define XS_LD 20   // padded ld for x chunk (conflict-free scatter)

// Small scratch only (allocation-free rule: __device__ globals).
__device__ float g_KV[NJ * H * D * D];   // 33.5 MB, [(n*H+h)][m][d]
__device__ float g_Ksum[NJ * H * D];     // [(n*H+h)][d]

extern __shared__ float smem[];

__device__ __forceinline__ float elu1(float v) {
    return (v >= 0.f) ? (v + 1.f) : __expf(v);
}

// ---------------------------------------------------------------------------
// Kernel A: per (n,h), fused K/V projection + KV outer-product reduction.
//   KV[m][d] = sum_f V[f][m] * K[f][d],  Ksum[d] = sum_f K[f][d]
//   K[f][d] = elu1(x[f,n,:] . Wk[:, h*D+d] + bk),  V likewise (no act).
// 256 threads, 8x8 microtiles. f streamed in 128-row chunks.
// ---------------------------------------------------------------------------
__global__ __launch_bounds__(256) void kv_fused(
    const float* __restrict__ x,
    const float* __restrict__ Wk, const float* __restrict__ bk,
    const float* __restrict__ Wv, const float* __restrict__ bv)
{
    const int n = blockIdx.x;
    const int h = blockIdx.y;
    const int t  = threadIdx.x;
    const int tx = t & 15;
    const int ty = t >> 4;

    float* xs = smem;                  // [128][XS_LD]
    float* Ws = xs + 128 * XS_LD;      // [16][128]
    float* Ks = Ws + 16 * 128;         // [128][128]  K tile [f][d]
    float* Vs = Ks + 128 * 128;        // [128][128]  V tile [f][m]

    float kvacc[8][8];
    #pragma unroll
    for (int i = 0; i < 8; i++)
        #pragma unroll
        for (int j = 0; j < 8; j++) kvacc[i][j] = 0.f;
    float ksum = 0.f;

    for (int f0 = 0; f0 < F; f0 += 128) {
        // ---- Phase 1: project K tile then V tile into smem ----
        #pragma unroll 1
        for (int mtx = 0; mtx < 2; mtx++) {
            const float* __restrict__ W    = mtx ? Wv : Wk;
            const float* __restrict__ bias = mtx ? bv : bk;
            float* __restrict__ Out        = mtx ? Vs : Ks;

            float acc[8][8];
            #pragma unroll
            for (int i = 0; i < 8; i++)
                #pragma unroll
                for (int j = 0; j < 8; j++) acc[i][j] = 0.f;

            for (int c0 = 0; c0 < C; c0 += 16) {
                __syncthreads();
                // x chunk: 128 f-rows x 16 c-cols (row-major, padded ld)
                #pragma unroll
                for (int it = 0; it < 2; it++) {
                    int idx = t + it * 256;
                    int row = idx >> 2, c4 = idx & 3;
                    float4 v = *(const float4*)
                        &x[((size_t)(f0 + row) * NJ + n) * C + c0 + c4 * 4];
                    *(float4*)&xs[row * XS_LD + c4 * 4] = v;
                }
                // W chunk: 16 c-rows x 128 cols of this head's slice
                #pragma unroll
                for (int it = 0; it < 2; it++) {
                    int idx = t + it * 256;
                    int row = idx >> 5, c4 = idx & 31;
                    *(float4*)&Ws[row * 128 + c4 * 4] =
                        *(const float4*)&W[(size_t)(c0 + row) * HID + h * D + c4 * 4];
                }
                __syncthreads();

                #pragma unroll
                for (int kk = 0; kk < 16; kk++) {
                    float a[8], b[8];
                    #pragma unroll
                    for (int i = 0; i < 8; i++)
                        a[i] = xs[(ty * 8 + i) * XS_LD + kk];   // broadcast
                    *(float4*)&b[0] = *(float4*)&Ws[kk * 128 + tx * 8];
                    *(float4*)&b[4] = *(float4*)&Ws[kk * 128 + tx * 8 + 4];
                    #pragma unroll
                    for (int i = 0; i < 8; i++)
                        #pragma unroll
                        for (int j = 0; j < 8; j++)
                            acc[i][j] += a[i] * b[j];
                }
            }
            // Epilogue: bias (+ feature map for K), store tile row-major
            #pragma unroll
            for (int i = 0; i < 8; i++) {
                float4 o[2];
                float* of = (float*)o;
                #pragma unroll
                for (int j = 0; j < 8; j++) {
                    float v = acc[i][j] + bias[h * D + tx * 8 + j];
                    of[j] = (mtx == 0) ? elu1(v) : v;
                }
                *(float4*)&Out[(ty * 8 + i) * 128 + tx * 8 + 0] = o[0];
                *(float4*)&Out[(ty * 8 + i) * 128 + tx * 8 + 4] = o[1];
            }
        }
        __syncthreads();   // K/V tiles complete & visible

        // ---- Ksum partial (threads 0..127 own one d each) ----
        if (t < 128) {
            #pragma unroll 8
            for (int ff = 0; ff < 128; ff++) ksum += Ks[ff * 128 + t];
        }

        // ---- Phase 2: KV[m][d] += V[f][m] * K[f][d] over this chunk ----
        #pragma unroll 4
        for (int ff = 0; ff < 128; ff++) {
            float a[8], b[8];
            *(float4*)&a[0] = *(float4*)&Vs[ff * 128 + ty * 8];
            *(float4*)&a[4] = *(float4*)&Vs[ff * 128 + ty * 8 + 4];
            *(float4*)&b[0] = *(float4*)&Ks[ff * 128 + tx * 8];
            *(float4*)&b[4] = *(float4*)&Ks[ff * 128 + tx * 8 + 4];
            #pragma unroll
            for (int i = 0; i < 8; i++)
                #pragma unroll
                for (int j = 0; j < 8; j++)
                    kvacc[i][j] += a[i] * b[j];
        }
        __syncthreads();   // done reading K/V tiles before next chunk
    }

    const int nh = n * H + h;
    #pragma unroll
    for (int i = 0; i < 8; i++) {
        #pragma unroll
        for (int j = 0; j < 2; j++) {
            float4 v = make_float4(kvacc[i][j*4+0], kvacc[i][j*4+1],
                                   kvacc[i][j*4+2], kvacc[i][j*4+3]);
            *(float4*)&g_KV[(size_t)nh * D * D + (ty * 8 + i) * D + tx * 8 + j * 4] = v;
        }
    }
    if (t < 128) g_Ksum[(size_t)nh * D + t] = ksum;
}

// ---------------------------------------------------------------------------
// Kernel B: per (l-tile, n, h), fused Q projection + output GEMM + Z.
//   out[l][m] = (Q[l,:] . KV[m,:]) / (Q[l,:] . Ksum + eps)
// ---------------------------------------------------------------------------
__global__ __launch_bounds__(256) void out_fused(
    const float* __restrict__ x,
    const float* __restrict__ Wq, const float* __restrict__ bq,
    float* __restrict__ out)
{
    const int l0 = blockIdx.x * 128;
    const int n  = blockIdx.y;
    const int h  = blockIdx.z;
    const int nh = n * H + h;
    const int t  = threadIdx.x;
    const int tx = t & 15;
    const int ty = t >> 4;

    float* Qs  = smem;                 // [128][128]  Q tile [l][d]
    float* KVs = Qs + 128 * 128;       // [128][128]  KV transposed [d][m]
    float* xs  = KVs + 128 * 128;      // [128][XS_LD]
    float* Ws  = xs + 128 * XS_LD;     // [16][128]
    float* ks  = Ws + 16 * 128;        // [128]

    // Load KV transposed ([m][d] -> KVs[d][m]); one-time scatter.
    #pragma unroll
    for (int it = 0; it < 16; it++) {
        int idx = t + it * 256;
        int m = idx >> 5, c4 = idx & 31;
        float4 v = *(const float4*)&g_KV[(size_t)nh * D * D + m * D + c4 * 4];
        KVs[(c4 * 4 + 0) * 128 + m] = v.x;
        KVs[(c4 * 4 + 1) * 128 + m] = v.y;
        KVs[(c4 * 4 + 2) * 128 + m] = v.z;
        KVs[(c4 * 4 + 3) * 128 + m] = v.w;
    }
    if (t < 128) ks[t] = g_Ksum[(size_t)nh * D + t];

    // ---- Phase 1: Q tile = elu1(x . Wq_h + bq_h) ----
    {
        float acc[8][8];
        #pragma unroll
        for (int i = 0; i < 8; i++)
            #pragma unroll
            for (int j = 0; j < 8; j++) acc[i][j] = 0.f;

        for (int c0 = 0; c0 < C; c0 += 16) {
            __syncthreads();
            #pragma unroll
            for (int it = 0; it < 2; it++) {
                int idx = t + it * 256;
                int row = idx >> 2, c4 = idx & 3;
                float4 v = *(const float4*)
                    &x[((size_t)(l0 + row) * NJ + n) * C + c0 + c4 * 4];
                *(float4*)&xs[row * XS_LD + c4 * 4] = v;
            }
            #pragma unroll
            for (int it = 0; it < 2; it++) {
                int idx = t + it * 256;
                int row = idx >> 5, c4 = idx & 31;
                *(float4*)&Ws[row * 128 + c4 * 4] =
                    *(const float4*)&Wq[(size_t)(c0 + row) * HID + h * D + c4 * 4];
            }
            __syncthreads();

            #pragma unroll
            for (int kk = 0; kk < 16; kk++) {
                float a[8], b[8];
                #pragma unroll
                for (int i = 0; i < 8; i++)
                    a[i] = xs[(ty * 8 + i) * XS_LD + kk];
                *(float4*)&b[0] = *(float4*)&Ws[kk * 128 + tx * 8];
                *(float4*)&b[4] = *(float4*)&Ws[kk * 128 + tx * 8 + 4];
                #pragma unroll
                for (int i = 0; i < 8; i++)
                    #pragma unroll
                    for (int j = 0; j < 8; j++)
                        acc[i][j] += a[i] * b[j];
            }
        }
        #pragma unroll
        for (int i = 0; i < 8; i++) {
            float4 o[2];
            float* of = (float*)o;
            #pragma unroll
            for (int j = 0; j < 8; j++)
                of[j] = elu1(acc[i][j] + bq[h * D + tx * 8 + j]);
            *(float4*)&Qs[(ty * 8 + i) * 128 + tx * 8 + 0] = o[0];
            *(float4*)&Qs[(ty * 8 + i) * 128 + tx * 8 + 4] = o[1];
        }
    }
    __syncthreads();   // Qs + KVs + ks all visible

    // ---- Phase 2: out = Q . KV^T with fused Z ----
    float acc2[8][8];
    #pragma unroll
    for (int i = 0; i < 8; i++)
        #pragma unroll
        for (int j = 0; j < 8; j++) acc2[i][j] = 0.f;
    float zacc[8] = {0.f,0.f,0.f,0.f,0.f,0.f,0.f,0.f};

    #pragma unroll 4
    for (int dd = 0; dd < 128; dd++) {
        float a[8], b[8];
        #pragma unroll
        for (int i = 0; i < 8; i++)
            a[i] = Qs[(ty * 8 + i) * 128 + dd];     // broadcast reads
        *(float4*)&b[0] = *(float4*)&KVs[dd * 128 + tx * 8];
        *(float4*)&b[4] = *(float4*)&KVs[dd * 128 + tx * 8 + 4];
        const float kss = ks[dd];
        #pragma unroll
        for (int i = 0; i < 8; i++) {
            zacc[i] += a[i] * kss;
            #pragma unroll
            for (int j = 0; j < 8; j++)
                acc2[i][j] += a[i] * b[j];
        }
    }

    #pragma unroll
    for (int i = 0; i < 8; i++) {
        const float zinv = 1.f / (zacc[i] + 1e-6f);
        const int l = l0 + ty * 8 + i;
        float4 o[2];
        float* of = (float*)o;
        #pragma unroll
        for (int j = 0; j < 8; j++) of[j] = acc2[i][j] * zinv;
        size_t base = ((size_t)l * NJ + n) * HID + h * D + tx * 8;
        *(float4*)&out[base + 0] = o[0];
        *(float4*)&out[base + 4] = o[1];
    }
}

// ---------------------------------------------------------------------------
extern "C" void kernel_launch(void* const* d_in, const int* in_sizes, int n_in,
                              void* d_out, int out_size)
{
    const float* x  = (const float*)d_in[0];
    const float* Wq = (const float*)d_in[1];
    const float* bq = (const float*)d_in[2];
    const float* Wk = (const float*)d_in[3];
    const float* bk = (const float*)d_in[4];
    const float* Wv = (const float*)d_in[5];
    const float* bv = (const float*)d_in[6];
    float* out = (float*)d_out;

    const int smem_a = (128 * XS_LD + 16 * 128 + 2 * 128 * 128) * 4;   // 149504
    const int smem_b = (2 * 128 * 128 + 128 * XS_LD + 16 * 128 + 128) * 4; // 150016

    cudaFuncSetAttribute(kv_fused,  cudaFuncAttributeMaxDynamicSharedMemorySize, smem_a);
    cudaFuncSetAttribute(out_fused, cudaFuncAttributeMaxDynamicSharedMemorySize, smem_b);

    kv_fused<<<dim3(NJ, H), 256, smem_a>>>(x, Wk, bk, Wv, bv);
    out_fused<<<dim3(F / 128, NJ, H), 256, smem_b>>>(x, Wq, bq, out);
}

// round 8
// speedup vs baseline: 1.1635x; 1.1635x over previous
#include <cuda_runtime.h>
#include <math.h>

#define F    1024
#define NJ   64
#define C    256
#define HID  1024
#define H    8
#define D    128
#define PARTS 2
#define FP   (F / PARTS)   // 512

#define XS_LD 20   // padded ld for x chunk

// Scratch (allocation-free rule: __device__ globals). 67 MB total.
__device__ float g_KVp[(size_t)PARTS * NJ * H * D * D];  // [p][(n*H+h)][m][d]
__device__ float g_Ksp[(size_t)PARTS * NJ * H * D];      // [p][(n*H+h)][d]

extern __shared__ float smem[];

__device__ __forceinline__ float elu1(float v) {
    return (v >= 0.f) ? (v + 1.f) : __expf(v);
}

// Packed dual fp32 FMA: d = a*b + d elementwise on (x,y) lanes.
__device__ __forceinline__ void fma2(float2& d, const float2 a, const float2 b) {
    asm("fma.rn.f32x2 %0, %1, %2, %0;"
        : "+l"(reinterpret_cast<unsigned long long&>(d))
        : "l"(reinterpret_cast<const unsigned long long&>(a)),
          "l"(reinterpret_cast<const unsigned long long&>(b)));
}

__device__ __forceinline__ float2 dup2(float v) { return make_float2(v, v); }

// ---------------------------------------------------------------------------
// Kernel A: per (n,h,p): fused K/V projection + partial KV outer product.
//   KVp[m][d] = sum_{f in part} V[f][m] * K[f][d],  Kps[d] = sum K[f][d]
// 256 threads, 8x8 microtile via packed f32x2 (acc pairs along columns).
// ---------------------------------------------------------------------------
__global__ __launch_bounds__(256) void kv_fused(
    const float* __restrict__ x,
    const float* __restrict__ Wk, const float* __restrict__ bk,
    const float* __restrict__ Wv, const float* __restrict__ bv)
{
    const int n = blockIdx.x;
    const int h = blockIdx.y;
    const int p = blockIdx.z;
    const int t  = threadIdx.x;
    const int tx = t & 15;
    const int ty = t >> 4;

    float* xs = smem;                  // [128][XS_LD]
    float* Ws = xs + 128 * XS_LD;      // [16][128]
    float* Ks = Ws + 16 * 128;         // [128][128]  K tile [f][d]
    float* Vs = Ks + 128 * 128;        // [128][128]  V tile [f][m]

    float2 kvacc[8][4];
    #pragma unroll
    for (int i = 0; i < 8; i++)
        #pragma unroll
        for (int j = 0; j < 4; j++) kvacc[i][j] = make_float2(0.f, 0.f);
    float ksum = 0.f;

    for (int f0 = p * FP; f0 < p * FP + FP; f0 += 128) {
        // ---- Phase 1: project K tile then V tile into smem ----
        #pragma unroll 1
        for (int mtx = 0; mtx < 2; mtx++) {
            const float* __restrict__ W    = mtx ? Wv : Wk;
            const float* __restrict__ bias = mtx ? bv : bk;
            float* __restrict__ Out        = mtx ? Vs : Ks;

            float2 acc[8][4];
            #pragma unroll
            for (int i = 0; i < 8; i++)
                #pragma unroll
                for (int j = 0; j < 4; j++) acc[i][j] = make_float2(0.f, 0.f);

            for (int c0 = 0; c0 < C; c0 += 16) {
                __syncthreads();
                #pragma unroll
                for (int it = 0; it < 2; it++) {
                    int idx = t + it * 256;
                    int row = idx >> 2, c4 = idx & 3;
                    float4 v = *(const float4*)
                        &x[((size_t)(f0 + row) * NJ + n) * C + c0 + c4 * 4];
                    *(float4*)&xs[row * XS_LD + c4 * 4] = v;
                }
                #pragma unroll
                for (int it = 0; it < 2; it++) {
                    int idx = t + it * 256;
                    int row = idx >> 5, c4 = idx & 31;
                    *(float4*)&Ws[row * 128 + c4 * 4] =
                        *(const float4*)&W[(size_t)(c0 + row) * HID + h * D + c4 * 4];
                }
                __syncthreads();

                #pragma unroll
                for (int kk = 0; kk < 16; kk++) {
                    float av[8];
                    #pragma unroll
                    for (int i = 0; i < 8; i++)
                        av[i] = xs[(ty * 8 + i) * XS_LD + kk];
                    float4 w0 = *(float4*)&Ws[kk * 128 + tx * 8];
                    float4 w1 = *(float4*)&Ws[kk * 128 + tx * 8 + 4];
                    float2 b2[4] = { make_float2(w0.x, w0.y), make_float2(w0.z, w0.w),
                                     make_float2(w1.x, w1.y), make_float2(w1.z, w1.w) };
                    #pragma unroll
                    for (int i = 0; i < 8; i++) {
                        float2 ad = dup2(av[i]);
                        #pragma unroll
                        for (int j = 0; j < 4; j++) fma2(acc[i][j], ad, b2[j]);
                    }
                }
            }
            // Epilogue: bias (+ feature map for K), store tile row-major
            #pragma unroll
            for (int i = 0; i < 8; i++) {
                float vals[8] = { acc[i][0].x, acc[i][0].y, acc[i][1].x, acc[i][1].y,
                                  acc[i][2].x, acc[i][2].y, acc[i][3].x, acc[i][3].y };
                float4 o[2];
                float* of = (float*)o;
                #pragma unroll
                for (int j = 0; j < 8; j++) {
                    float v = vals[j] + bias[h * D + tx * 8 + j];
                    of[j] = (mtx == 0) ? elu1(v) : v;
                }
                *(float4*)&Out[(ty * 8 + i) * 128 + tx * 8 + 0] = o[0];
                *(float4*)&Out[(ty * 8 + i) * 128 + tx * 8 + 4] = o[1];
            }
        }
        __syncthreads();

        if (t < 128) {
            #pragma unroll 8
            for (int ff = 0; ff < 128; ff++) ksum += Ks[ff * 128 + t];
        }

        // ---- Phase 2: KVp[m][d] += V[f][m] * K[f][d] ----
        #pragma unroll 4
        for (int ff = 0; ff < 128; ff++) {
            float4 a0 = *(float4*)&Vs[ff * 128 + ty * 8];
            float4 a1 = *(float4*)&Vs[ff * 128 + ty * 8 + 4];
            float4 k0 = *(float4*)&Ks[ff * 128 + tx * 8];
            float4 k1 = *(float4*)&Ks[ff * 128 + tx * 8 + 4];
            float av[8] = { a0.x, a0.y, a0.z, a0.w, a1.x, a1.y, a1.z, a1.w };
            float2 b2[4] = { make_float2(k0.x, k0.y), make_float2(k0.z, k0.w),
                             make_float2(k1.x, k1.y), make_float2(k1.z, k1.w) };
            #pragma unroll
            for (int i = 0; i < 8; i++) {
                float2 ad = dup2(av[i]);
                #pragma unroll
                for (int j = 0; j < 4; j++) fma2(kvacc[i][j], ad, b2[j]);
            }
        }
        __syncthreads();
    }

    const int nh = n * H + h;
    const size_t base = ((size_t)(p * NJ * H) + nh) * D * D;
    #pragma unroll
    for (int i = 0; i < 8; i++) {
        float4 v0 = make_float4(kvacc[i][0].x, kvacc[i][0].y, kvacc[i][1].x, kvacc[i][1].y);
        float4 v1 = make_float4(kvacc[i][2].x, kvacc[i][2].y, kvacc[i][3].x, kvacc[i][3].y);
        *(float4*)&g_KVp[base + (ty * 8 + i) * D + tx * 8 + 0] = v0;
        *(float4*)&g_KVp[base + (ty * 8 + i) * D + tx * 8 + 4] = v1;
    }
    if (t < 128) g_Ksp[((size_t)p * NJ * H + nh) * D + t] = ksum;
}

// ---------------------------------------------------------------------------
// Kernel B: per (l-tile, n, h): fused Q projection + output GEMM + Z.
// KV/Ksum partials summed at load. Packed f32x2 mainloops.
// ---------------------------------------------------------------------------
__global__ __launch_bounds__(256) void out_fused(
    const float* __restrict__ x,
    const float* __restrict__ Wq, const float* __restrict__ bq,
    float* __restrict__ out)
{
    const int l0 = blockIdx.x * 128;
    const int n  = blockIdx.y;
    const int h  = blockIdx.z;
    const int nh = n * H + h;
    const int t  = threadIdx.x;
    const int tx = t & 15;
    const int ty = t >> 4;

    float* Qs  = smem;                 // [128][128]  Q tile [l][d]
    float* KVs = Qs + 128 * 128;       // [128][128]  KV transposed [d][m]
    float* xs  = KVs + 128 * 128;      // [128][XS_LD]
    float* Ws  = xs + 128 * XS_LD;     // [16][128]
    float* ks  = Ws + 16 * 128;        // [128]

    // Load KV (= p0 + p1), transposed [m][d] -> KVs[d][m].
    const size_t kvb = (size_t)nh * D * D;
    #pragma unroll
    for (int it = 0; it < 16; it++) {
        int idx = t + it * 256;
        int m = idx >> 5, c4 = idx & 31;
        float4 a = *(const float4*)&g_KVp[kvb + m * D + c4 * 4];
        float4 b = *(const float4*)&g_KVp[(size_t)NJ * H * D * D + kvb + m * D + c4 * 4];
        KVs[(c4 * 4 + 0) * 128 + m] = a.x + b.x;
        KVs[(c4 * 4 + 1) * 128 + m] = a.y + b.y;
        KVs[(c4 * 4 + 2) * 128 + m] = a.z + b.z;
        KVs[(c4 * 4 + 3) * 128 + m] = a.w + b.w;
    }
    if (t < 128)
        ks[t] = g_Ksp[(size_t)nh * D + t] +
                g_Ksp[(size_t)NJ * H * D + nh * D + t];

    // ---- Phase 1: Q tile = elu1(x . Wq_h + bq_h) ----
    {
        float2 acc[8][4];
        #pragma unroll
        for (int i = 0; i < 8; i++)
            #pragma unroll
            for (int j = 0; j < 4; j++) acc[i][j] = make_float2(0.f, 0.f);

        for (int c0 = 0; c0 < C; c0 += 16) {
            __syncthreads();
            #pragma unroll
            for (int it = 0; it < 2; it++) {
                int idx = t + it * 256;
                int row = idx >> 2, c4 = idx & 3;
                float4 v = *(const float4*)
                    &x[((size_t)(l0 + row) * NJ + n) * C + c0 + c4 * 4];
                *(float4*)&xs[row * XS_LD + c4 * 4] = v;
            }
            #pragma unroll
            for (int it = 0; it < 2; it++) {
                int idx = t + it * 256;
                int row = idx >> 5, c4 = idx & 31;
                *(float4*)&Ws[row * 128 + c4 * 4] =
                    *(const float4*)&Wq[(size_t)(c0 + row) * HID + h * D + c4 * 4];
            }
            __syncthreads();

            #pragma unroll
            for (int kk = 0; kk < 16; kk++) {
                float av[8];
                #pragma unroll
                for (int i = 0; i < 8; i++)
                    av[i] = xs[(ty * 8 + i) * XS_LD + kk];
                float4 w0 = *(float4*)&Ws[kk * 128 + tx * 8];
                float4 w1 = *(float4*)&Ws[kk * 128 + tx * 8 + 4];
                float2 b2[4] = { make_float2(w0.x, w0.y), make_float2(w0.z, w0.w),
                                 make_float2(w1.x, w1.y), make_float2(w1.z, w1.w) };
                #pragma unroll
                for (int i = 0; i < 8; i++) {
                    float2 ad = dup2(av[i]);
                    #pragma unroll
                    for (int j = 0; j < 4; j++) fma2(acc[i][j], ad, b2[j]);
                }
            }
        }
        #pragma unroll
        for (int i = 0; i < 8; i++) {
            float vals[8] = { acc[i][0].x, acc[i][0].y, acc[i][1].x, acc[i][1].y,
                              acc[i][2].x, acc[i][2].y, acc[i][3].x, acc[i][3].y };
            float4 o[2];
            float* of = (float*)o;
            #pragma unroll
            for (int j = 0; j < 8; j++)
                of[j] = elu1(vals[j] + bq[h * D + tx * 8 + j]);
            *(float4*)&Qs[(ty * 8 + i) * 128 + tx * 8 + 0] = o[0];
            *(float4*)&Qs[(ty * 8 + i) * 128 + tx * 8 + 4] = o[1];
        }
    }
    __syncthreads();

    // ---- Phase 2: out = Q . KV^T with fused Z ----
    float2 acc2[8][4];
    #pragma unroll
    for (int i = 0; i < 8; i++)
        #pragma unroll
        for (int j = 0; j < 4; j++) acc2[i][j] = make_float2(0.f, 0.f);
    float zacc[8] = {0.f,0.f,0.f,0.f,0.f,0.f,0.f,0.f};

    #pragma unroll 4
    for (int dd = 0; dd < 128; dd++) {
        float av[8];
        #pragma unroll
        for (int i = 0; i < 8; i++)
            av[i] = Qs[(ty * 8 + i) * 128 + dd];
        float4 b0 = *(float4*)&KVs[dd * 128 + tx * 8];
        float4 b1 = *(float4*)&KVs[dd * 128 + tx * 8 + 4];
        float2 b2[4] = { make_float2(b0.x, b0.y), make_float2(b0.z, b0.w),
                         make_float2(b1.x, b1.y), make_float2(b1.z, b1.w) };
        const float kss = ks[dd];
        #pragma unroll
        for (int i = 0; i < 8; i++) {
            zacc[i] += av[i] * kss;
            float2 ad = dup2(av[i]);
            #pragma unroll
            for (int j = 0; j < 4; j++) fma2(acc2[i][j], ad, b2[j]);
        }
    }

    #pragma unroll
    for (int i = 0; i < 8; i++) {
        const float zinv = 1.f / (zacc[i] + 1e-6f);
        const int l = l0 + ty * 8 + i;
        float4 o0 = make_float4(acc2[i][0].x * zinv, acc2[i][0].y * zinv,
                                acc2[i][1].x * zinv, acc2[i][1].y * zinv);
        float4 o1 = make_float4(acc2[i][2].x * zinv, acc2[i][2].y * zinv,
                                acc2[i][3].x * zinv, acc2[i][3].y * zinv);
        size_t base = ((size_t)l * NJ + n) * HID + h * D + tx * 8;
        *(float4*)&out[base + 0] = o0;
        *(float4*)&out[base + 4] = o1;
    }
}

// ---------------------------------------------------------------------------
extern "C" void kernel_launch(void* const* d_in, const int* in_sizes, int n_in,
                              void* d_out, int out_size)
{
    const float* x  = (const float*)d_in[0];
    const float* Wq = (const float*)d_in[1];
    const float* bq = (const float*)d_in[2];
    const float* Wk = (const float*)d_in[3];
    const float* bk = (const float*)d_in[4];
    const float* Wv = (const float*)d_in[5];
    const float* bv = (const float*)d_in[6];
    float* out = (float*)d_out;

    const int smem_a = (128 * XS_LD + 16 * 128 + 2 * 128 * 128) * 4;       // 149504
    const int smem_b = (2 * 128 * 128 + 128 * XS_LD + 16 * 128 + 128) * 4; // 150016

    cudaFuncSetAttribute(kv_fused,  cudaFuncAttributeMaxDynamicSharedMemorySize, smem_a);
    cudaFuncSetAttribute(out_fused, cudaFuncAttributeMaxDynamicSharedMemorySize, smem_b);

    kv_fused<<<dim3(NJ, H, PARTS), 256, smem_a>>>(x, Wk, bk, Wv, bv);
    out_fused<<<dim3(F / 128, NJ, H), 256, smem_b>>>(x, Wq, bq, out);
}